// round 1
// baseline (speedup 1.0000x reference)
#include <cuda_runtime.h>
#include <cstdint>
#include <cstddef>

#define TAME_F  100000.0f
#define TAME2_F 1.0e10f

__device__ __forceinline__ float frsq(float x) {
    float r;
    asm("rsqrt.approx.f32 %0, %1;" : "=f"(r) : "f"(x));
    return r;
}

// One thread = one system. 128 threads/block -> 1 block/SM, 1 warp/SMSP:
// the per-step dependency chain is the limiter, so give each warp its own
// scheduler and keep everything else off the critical path.
__global__ void __launch_bounds__(128, 1)
tithte_kernel(const float* __restrict__ state0,
              const float* __restrict__ params,
              const float* __restrict__ ed,
              const int*   __restrict__ dtp,
              float*       __restrict__ out,
              int B, int T)
{
    extern __shared__ float sdata[];   // (T+2)*3 floats, rows: [T_out, heat, solar]

    const int tid = threadIdx.x;
    {
        // cooperative stage of external_data into smem (vectorized), pad 2 rows of zeros
        const int totalf = (T + 2) * 3;
        const int n3     = T * 3;
        const int nv4    = n3 >> 2;
        const float4* ed4 = (const float4*)ed;
        float4*       sd4 = (float4*)sdata;
        for (int i = tid; i < nv4; i += blockDim.x) sd4[i] = ed4[i];
        for (int i = (nv4 << 2) + tid; i < totalf; i += blockDim.x)
            sdata[i] = (i < n3) ? ed[i] : 0.0f;
    }
    __syncthreads();

    const int b = blockIdx.x * blockDim.x + tid;
    if (b >= B) return;

    const float dtf = (float)dtp[0];
    const float C1 = params[b*6+0], R1 = params[b*6+1];
    const float C2 = params[b*6+2], R2 = params[b*6+3];
    const float C3 = params[b*6+4], R3 = params[b*6+5];

    const float a1 = dtf / C1, a2 = dtf / C2, a3 = dtf / C3;
    const float iR1 = 1.0f / R1, iR2 = 1.0f / R2, iR3 = 1.0f / R3;

    // x = M*s + c  with  x1 = dT_in, x2 = dT_heater, x3 = dT_env (pre-tame)
    const float m12 = a1 * iR2, m13 = a1 * iR1, m11 = -(m12 + m13);
    const float m21 = a2 * iR2, m22 = -m21;
    const float m31 = a3 * iR1, k33 = a3 * iR3, m33 = -(m31 + k33);

    float s1 = state0[b*3+0], s2 = state0[b*3+1], s3 = state0[b*3+2];

    // prologue: x(0) from data row 0
    float c1 = a1  * sdata[2];   // solar
    float c2 = a2  * sdata[1];   // heat
    float c3 = k33 * sdata[0];   // T_out
    float x1 = fmaf(m13, s3, fmaf(m12, s2, fmaf(m11, s1, c1)));
    float x2 = fmaf(m22, s2, fmaf(m21, s1, c2));
    float x3 = fmaf(m33, s3, fmaf(m31, s1, c3));
    float h1 = fmaf(x1, x1, TAME2_F), tx1 = x1 * TAME_F;
    float h2 = fmaf(x2, x2, TAME2_F), tx2 = x2 * TAME_F;
    float h3 = fmaf(x3, x3, TAME2_F), tx3 = x3 * TAME_F;

    // prefetch data row 1
    float nO = sdata[3], nH = sdata[4], nS = sdata[5];

    float* outp = out + (size_t)b * 3;
    const size_t ostride = (size_t)B * 3;

    #pragma unroll 4
    for (int t = 0; t < T; ++t) {
        // tame + state update. rsqrt(h1) issued first: every x(t+1) needs s1'.
        const float r1 = frsq(h1);
        const float r2 = frsq(h2);
        const float r3 = frsq(h3);
        s1 = fmaf(tx1, r1, s1);
        s2 = fmaf(tx2, r2, s2);
        s3 = fmaf(tx3, r3, s3);

        outp[0] = s1;
        outp[1] = s2;
        outp[2] = s3;
        outp += ostride;

        // c for step t+1 from prefetched row (off critical path)
        c1 = a1  * nS;
        c2 = a2  * nH;
        c3 = k33 * nO;
        // prefetch row t+2 (smem is zero-padded past T)
        const float* rw = sdata + (t + 2) * 3;
        nO = rw[0]; nH = rw[1]; nS = rw[2];

        // x(t+1) = M*s(t+1) + c(t+1), accumulated in s'-arrival order (s1 first, s3 last)
        x1 = fmaf(m13, s3, fmaf(m12, s2, fmaf(m11, s1, c1)));
        x2 = fmaf(m22, s2, fmaf(m21, s1, c2));
        x3 = fmaf(m33, s3, fmaf(m31, s1, c3));

        h1 = fmaf(x1, x1, TAME2_F); tx1 = x1 * TAME_F;
        h2 = fmaf(x2, x2, TAME2_F); tx2 = x2 * TAME_F;
        h3 = fmaf(x3, x3, TAME2_F); tx3 = x3 * TAME_F;
    }
}

extern "C" void kernel_launch(void* const* d_in, const int* in_sizes, int n_in,
                              void* d_out, int out_size) {
    const float* state0 = (const float*)d_in[0];
    const float* params = (const float*)d_in[1];
    const float* ed     = (const float*)d_in[2];
    const int*   dtp    = (const int*)d_in[3];
    float* out = (float*)d_out;

    const int B = in_sizes[0] / 3;   // state0 is (B, 3)
    const int T = in_sizes[2] / 3;   // external_data is (T, 3)

    const int threads = 128;
    const int blocks  = (B + threads - 1) / threads;
    const size_t smem = (size_t)(T + 2) * 3 * sizeof(float);

    cudaFuncSetAttribute(tithte_kernel,
                         cudaFuncAttributeMaxDynamicSharedMemorySize, (int)smem);
    tithte_kernel<<<blocks, threads, smem>>>(state0, params, ed, dtp, out, B, T);
}